// round 8
// baseline (speedup 1.0000x reference)
#include <cuda_runtime.h>
#include <cuda_bf16.h>
#include <cstdint>

// Problem dims
#define BB 2
#define SS 2048
#define HH 1024
#define NH 16
#define DD 64
#define MM (BB * SS)       // 4096 rows
#define K3H (3 * HH)       // 3072

// GEMM tiling: 128x128 CTA, 4 warps, 64x64 warp tile
#define MT 128
#define NT 128
#define KC 16
#define NCHUNK (HH / KC)   // 64
#define LDS_PAD 20         // stride mod 32 == 4*k -> LDSM conflict-free

// Scratch (device globals; no allocation allowed)
__device__ float g_q[BB * NH * SS * DD];   // [b][n][s][d], pre-scaled by D^-0.5
__device__ float g_k[BB * NH * SS * DD];   // [b][n][s][d]
__device__ float g_v[BB * NH * DD * SS];   // [b][n][d][s]  (d-major for PV ldmatrix)
__device__ float g_o[MM * HH];             // [b*s][h] with h = n*64 + d

__device__ __forceinline__ uint32_t f2tf32(float x) {
    uint32_t r;
    asm("cvt.rna.tf32.f32 %0, %1;" : "=r"(r) : "f"(x));
    return r;
}
__device__ __forceinline__ float tf32f(float x) { return __uint_as_float(f2tf32(x)); }

__device__ __forceinline__ void mma_tf32(float* d, const uint32_t* a, const uint32_t* b) {
    asm volatile(
        "mma.sync.aligned.m16n8k8.row.col.f32.tf32.tf32.f32 "
        "{%0,%1,%2,%3}, {%4,%5,%6,%7}, {%8,%9}, {%0,%1,%2,%3};"
        : "+f"(d[0]), "+f"(d[1]), "+f"(d[2]), "+f"(d[3])
        : "r"(a[0]), "r"(a[1]), "r"(a[2]), "r"(a[3]), "r"(b[0]), "r"(b[1]));
}

__device__ __forceinline__ void ldsm4(uint32_t* r, const void* p) {
    uint32_t a = (uint32_t)__cvta_generic_to_shared(p);
    asm volatile("ldmatrix.sync.aligned.m8n8.x4.shared.b16 {%0,%1,%2,%3}, [%4];"
                 : "=r"(r[0]), "=r"(r[1]), "=r"(r[2]), "=r"(r[3]) : "r"(a));
}

// ---------------------------------------------------------------------------
// tf32 mma.sync GEMM, 64x64 warp tiles (4 warps / 128 threads per CTA).
// MODE 0: A = hs arg; scatter epilogue to g_q/g_k (s-major) and g_v (d-major).
// MODE 1: A = g_o (device-resolved); Y = C + bias.
// ---------------------------------------------------------------------------
template <int MODE>
__global__ void __launch_bounds__(128)
gemm_mma(const float* __restrict__ A, const float* __restrict__ W,
         const float* __restrict__ bias, float* __restrict__ Y)
{
    __shared__ float Asm[2][MT][LDS_PAD];
    __shared__ float Bsm[2][NT][LDS_PAD];

    const float* Aptr = (MODE == 1) ? (const float*)g_o : A;

    const int t    = threadIdx.x;
    const int wid  = t >> 5;
    const int lane = t & 31;
    const int g    = lane >> 2;
    const int c    = lane & 3;
    const int wm   = (wid >> 1) * 64;
    const int wn   = (wid & 1) * 64;
    const int m0   = blockIdx.y * MT;
    const int n0   = blockIdx.x * NT;

    const int a_row = ((lane >> 3) & 1) * 8 + (lane & 7);
    const int a_kof = (lane >> 4) * 4;
    const int b_row = ((lane >> 4) & 1) * 8 + (lane & 7);
    const int b_kof = ((lane >> 3) & 1) * 4;

    // each thread owns one row of A-tile and one row of B-tile (128 threads)
    const float* Ag = Aptr + (long)(m0 + t) * HH;
    const float* Bg = W    + (long)(n0 + t) * HH;

    float acc[4][8][4];
#pragma unroll
    for (int mi = 0; mi < 4; mi++)
#pragma unroll
        for (int ni = 0; ni < 8; ni++)
#pragma unroll
            for (int k = 0; k < 4; k++) acc[mi][ni][k] = 0.f;

    float4 pa[4], pb[4];
#pragma unroll
    for (int p = 0; p < 4; p++) {
        pa[p] = *(const float4*)(Ag + p * 4);
        pb[p] = *(const float4*)(Bg + p * 4);
    }
#pragma unroll
    for (int p = 0; p < 4; p++) {
        uint4 wa = make_uint4(f2tf32(pa[p].x), f2tf32(pa[p].y), f2tf32(pa[p].z), f2tf32(pa[p].w));
        uint4 wb = make_uint4(f2tf32(pb[p].x), f2tf32(pb[p].y), f2tf32(pb[p].z), f2tf32(pb[p].w));
        *(uint4*)&Asm[0][t][p * 4] = wa;
        *(uint4*)&Bsm[0][t][p * 4] = wb;
    }
    __syncthreads();

#pragma unroll 1
    for (int kt = 0; kt < NCHUNK; kt++) {
        if (kt + 1 < NCHUNK) {
            const float* Agn = Ag + (kt + 1) * KC;
            const float* Bgn = Bg + (kt + 1) * KC;
#pragma unroll
            for (int p = 0; p < 4; p++) {
                pa[p] = *(const float4*)(Agn + p * 4);
                pb[p] = *(const float4*)(Bgn + p * 4);
            }
        }
        {
            const int st = kt & 1;
#pragma unroll
            for (int ks = 0; ks < 2; ks++) {
                const int k0 = ks * 8;
                uint32_t af[4][4], bf[4][4];
#pragma unroll
                for (int mi = 0; mi < 4; mi++)
                    ldsm4(af[mi], &Asm[st][wm + mi * 16 + a_row][k0 + a_kof]);
#pragma unroll
                for (int nj = 0; nj < 4; nj++)
                    ldsm4(bf[nj], &Bsm[st][wn + nj * 16 + b_row][k0 + b_kof]);
#pragma unroll
                for (int mi = 0; mi < 4; mi++)
#pragma unroll
                    for (int nj = 0; nj < 4; nj++) {
                        mma_tf32(acc[mi][nj * 2 + 0], af[mi], &bf[nj][0]);
                        mma_tf32(acc[mi][nj * 2 + 1], af[mi], &bf[nj][2]);
                    }
            }
        }
        if (kt + 1 < NCHUNK) {
            const int sn = (kt + 1) & 1;
#pragma unroll
            for (int p = 0; p < 4; p++) {
                uint4 wa = make_uint4(f2tf32(pa[p].x), f2tf32(pa[p].y), f2tf32(pa[p].z), f2tf32(pa[p].w));
                uint4 wb = make_uint4(f2tf32(pb[p].x), f2tf32(pb[p].y), f2tf32(pb[p].z), f2tf32(pb[p].w));
                *(uint4*)&Asm[sn][t][p * 4] = wa;
                *(uint4*)&Bsm[sn][t][p * 4] = wb;
            }
            __syncthreads();
        }
    }

    // Epilogue
#pragma unroll
    for (int ni = 0; ni < 8; ni++) {
        const int col = n0 + wn + ni * 8 + 2 * c;
        const float b0 = bias[col];
        const float b1 = bias[col + 1];
#pragma unroll
        for (int mi = 0; mi < 4; mi++) {
            const int r1 = m0 + wm + mi * 16 + g;
            const int r2 = r1 + 8;
            if (MODE == 0) {
                const int which = col >> 10;
                const int hn    = (col & 1023) >> 6;
                const int d     = col & 63;
                const float scale = (which == 0) ? 0.125f : 1.0f;
                const int bb1 = r1 >> 11, s1 = r1 & 2047;
                const int bb2 = r2 >> 11, s2 = r2 & 2047;
                float2 v1 = make_float2((acc[mi][ni][0] + b0) * scale,
                                        (acc[mi][ni][1] + b1) * scale);
                float2 v2 = make_float2((acc[mi][ni][2] + b0) * scale,
                                        (acc[mi][ni][3] + b1) * scale);
                if (which == 2) {
                    float* p1 = g_v + ((long)(bb1 * NH + hn) * DD + d) * SS + s1;
                    float* p2 = g_v + ((long)(bb2 * NH + hn) * DD + d) * SS + s2;
                    p1[0] = v1.x; p1[SS] = v1.y;
                    p2[0] = v2.x; p2[SS] = v2.y;
                } else {
                    float* dst0 = (which == 0) ? g_q : g_k;
                    *(float2*)(dst0 + (((long)(bb1 * NH + hn) * SS) + s1) * DD + d) = v1;
                    *(float2*)(dst0 + (((long)(bb2 * NH + hn) * SS) + s2) * DD + d) = v2;
                }
            } else {
                float2 v1 = make_float2(acc[mi][ni][0] + b0, acc[mi][ni][1] + b1);
                float2 v2 = make_float2(acc[mi][ni][2] + b0, acc[mi][ni][3] + b1);
                *(float2*)(Y + (long)r1 * HH + col) = v1;
                *(float2*)(Y + (long)r2 * HH + col) = v2;
            }
        }
    }
}

// ---------------------------------------------------------------------------
// Kernel 2: causal flash attention, tf32 mma.sync + ldmatrix + LDG prefetch.
// ---------------------------------------------------------------------------
__global__ __launch_bounds__(256) void flash_attn_mma()
{
    __shared__ float Ks[32][68];    // [kv][d]
    __shared__ float Vs[64][36];    // [d][kv]
    __shared__ float Ps[128][36];   // [qrow][kv]

    const int t    = threadIdx.x;
    const int wid  = t >> 5;
    const int lane = t & 31;
    const int g    = lane >> 2;
    const int c    = lane & 3;
    const int bn   = blockIdx.y;        // b*16+n
    const int q0   = blockIdx.x * 128;
    const int wr   = wid * 16;

    const int a_row = ((lane >> 3) & 1) * 8 + (lane & 7);
    const int a_kof = (lane >> 4) * 4;
    const int b_row = ((lane >> 4) & 1) * 8 + (lane & 7);
    const int b_kof = ((lane >> 3) & 1) * 4;

    const float* Qp = g_q + (long)bn * SS * DD;
    const float* Kp = g_k + (long)bn * SS * DD;
    const float* Vp = g_v + (long)bn * DD * SS;   // [d][s]

    // per-thread K/V load slots
    const int k_row0 = t >> 4;            // K rows for p=0 / +16 for p=1
    const int k_c4   = (t & 15) * 4;
    const int v_row0 = t >> 3;            // V d-rows for p=0 / +32 for p=1
    const int v_s4   = (t & 7) * 4;

    // Q fragments (tf32), loaded once
    uint32_t Qf[8][4];
    {
        const float* qr0 = Qp + (long)(q0 + wr + g) * DD;
        const float* qr1 = qr0 + 8 * DD;
#pragma unroll
        for (int kc = 0; kc < 8; kc++) {
            Qf[kc][0] = f2tf32(qr0[kc * 8 + c]);
            Qf[kc][1] = f2tf32(qr1[kc * 8 + c]);
            Qf[kc][2] = f2tf32(qr0[kc * 8 + c + 4]);
            Qf[kc][3] = f2tf32(qr1[kc * 8 + c + 4]);
        }
    }

    float O[8][4];
#pragma unroll
    for (int dn = 0; dn < 8; dn++)
#pragma unroll
        for (int k = 0; k < 4; k++) O[dn][k] = 0.f;
    float m0v = -1e30f, m1v = -1e30f, l0 = 0.f, l1 = 0.f;

    const int r0g = q0 + wr + g;
    const int r1g = r0g + 8;
    const int nkt = (q0 + 128) >> 5;

    // prologue: prefetch tile 0
    float4 ka[2], va[2];
#pragma unroll
    for (int p = 0; p < 2; p++) {
        ka[p] = *(const float4*)(Kp + (long)(k_row0 + p * 16) * DD + k_c4);
        va[p] = *(const float4*)(Vp + (long)(v_row0 + p * 32) * SS + v_s4);
    }

    for (int kt = 0; kt < nkt; kt++) {
        const int k0 = kt * 32;
        __syncthreads();                // prior tile's reads complete
#pragma unroll
        for (int p = 0; p < 2; p++) {
            float4 kv = ka[p];
            Ks[k_row0 + p * 16][k_c4 + 0] = tf32f(kv.x);
            Ks[k_row0 + p * 16][k_c4 + 1] = tf32f(kv.y);
            Ks[k_row0 + p * 16][k_c4 + 2] = tf32f(kv.z);
            Ks[k_row0 + p * 16][k_c4 + 3] = tf32f(kv.w);
            float4 vv = va[p];
            float4 w = make_float4(tf32f(vv.x), tf32f(vv.y), tf32f(vv.z), tf32f(vv.w));
            *(float4*)&Vs[v_row0 + p * 32][v_s4] = w;
        }
        __syncthreads();

        // prefetch next tile while computing this one
        if (kt + 1 < nkt) {
            const int kn = k0 + 32;
#pragma unroll
            for (int p = 0; p < 2; p++) {
                ka[p] = *(const float4*)(Kp + (long)(kn + k_row0 + p * 16) * DD + k_c4);
                va[p] = *(const float4*)(Vp + (long)(v_row0 + p * 32) * SS + kn + v_s4);
            }
        }

        // S = Q K^T
        float S[4][4];
#pragma unroll
        for (int ni = 0; ni < 4; ni++)
#pragma unroll
            for (int k = 0; k < 4; k++) S[ni][k] = 0.f;
#pragma unroll
        for (int kc = 0; kc < 8; kc++) {
            uint32_t bt[4];
            ldsm4(bt, &Ks[b_row][kc * 8 + b_kof]);
            mma_tf32(S[0], Qf[kc], &bt[0]);
            mma_tf32(S[1], Qf[kc], &bt[2]);
            ldsm4(bt, &Ks[16 + b_row][kc * 8 + b_kof]);
            mma_tf32(S[2], Qf[kc], &bt[0]);
            mma_tf32(S[3], Qf[kc], &bt[2]);
        }

        // causal mask + row max
        float mx0 = m0v, mx1 = m1v;
#pragma unroll
        for (int ni = 0; ni < 4; ni++) {
            const int col0 = k0 + ni * 8 + 2 * c;
            const int col1 = col0 + 1;
            if (col0 > r0g) S[ni][0] = -1e30f;
            if (col1 > r0g) S[ni][1] = -1e30f;
            if (col0 > r1g) S[ni][2] = -1e30f;
            if (col1 > r1g) S[ni][3] = -1e30f;
            mx0 = fmaxf(mx0, fmaxf(S[ni][0], S[ni][1]));
            mx1 = fmaxf(mx1, fmaxf(S[ni][2], S[ni][3]));
        }
        mx0 = fmaxf(mx0, __shfl_xor_sync(0xffffffffu, mx0, 1));
        mx0 = fmaxf(mx0, __shfl_xor_sync(0xffffffffu, mx0, 2));
        mx1 = fmaxf(mx1, __shfl_xor_sync(0xffffffffu, mx1, 1));
        mx1 = fmaxf(mx1, __shfl_xor_sync(0xffffffffu, mx1, 2));

        const float a0 = __expf(m0v - mx0);
        const float a1 = __expf(m1v - mx1);
        m0v = mx0; m1v = mx1;

        float rs0 = 0.f, rs1 = 0.f;
#pragma unroll
        for (int ni = 0; ni < 4; ni++) {
            float p00 = __expf(S[ni][0] - mx0);
            float p01 = __expf(S[ni][1] - mx0);
            float p10 = __expf(S[ni][2] - mx1);
            float p11 = __expf(S[ni][3] - mx1);
            rs0 += p00 + p01; rs1 += p10 + p11;
            *(float2*)&Ps[wr + g][ni * 8 + 2 * c]     = make_float2(tf32f(p00), tf32f(p01));
            *(float2*)&Ps[wr + g + 8][ni * 8 + 2 * c] = make_float2(tf32f(p10), tf32f(p11));
        }
        rs0 += __shfl_xor_sync(0xffffffffu, rs0, 1);
        rs0 += __shfl_xor_sync(0xffffffffu, rs0, 2);
        rs1 += __shfl_xor_sync(0xffffffffu, rs1, 1);
        rs1 += __shfl_xor_sync(0xffffffffu, rs1, 2);
        l0 = l0 * a0 + rs0;
        l1 = l1 * a1 + rs1;

#pragma unroll
        for (int dn = 0; dn < 8; dn++) {
            O[dn][0] *= a0; O[dn][1] *= a0;
            O[dn][2] *= a1; O[dn][3] *= a1;
        }
        __syncwarp();   // order Ps stores before ldmatrix reads (warp-private rows)

        // O += P @ V
#pragma unroll
        for (int j = 0; j < 4; j++) {
            uint32_t Af[4];
            ldsm4(Af, &Ps[wr + a_row][j * 8 + a_kof]);
#pragma unroll
            for (int dnp = 0; dnp < 4; dnp++) {
                uint32_t bt[4];
                ldsm4(bt, &Vs[dnp * 16 + b_row][j * 8 + b_kof]);
                mma_tf32(O[dnp * 2 + 0], Af, &bt[0]);
                mma_tf32(O[dnp * 2 + 1], Af, &bt[2]);
            }
        }
    }

    // epilogue: O /= l, write g_o[b*s][hn*64+d]
    const float inv0 = 1.0f / l0;
    const float inv1 = 1.0f / l1;
    const int b  = bn >> 4;
    const int hn = bn & 15;
    float* orow0 = g_o + (long)(b * SS + r0g) * HH + hn * DD;
    float* orow1 = orow0 + 8 * HH;
#pragma unroll
    for (int dn = 0; dn < 8; dn++) {
        *(float2*)(orow0 + dn * 8 + 2 * c) = make_float2(O[dn][0] * inv0, O[dn][1] * inv0);
        *(float2*)(orow1 + dn * 8 + 2 * c) = make_float2(O[dn][2] * inv1, O[dn][3] * inv1);
    }
}

// ---------------------------------------------------------------------------
extern "C" void kernel_launch(void* const* d_in, const int* in_sizes, int n_in,
                              void* d_out, int out_size)
{
    const float* hs    = (const float*)d_in[0];  // [B,S,H]
    const float* w_in  = (const float*)d_in[1];  // [3H,H]
    const float* b_in  = (const float*)d_in[2];  // [3H]
    const float* w_out = (const float*)d_in[3];  // [H,H]
    const float* b_out = (const float*)d_in[4];  // [H]
    float* out = (float*)d_out;                  // [B,S,H]

    (void)in_sizes; (void)n_in; (void)out_size;

    gemm_mma<0><<<dim3(K3H / NT, MM / MT), 128>>>(hs, w_in, b_in, nullptr);
    flash_attn_mma<<<dim3(SS / 128, BB * NH), 256>>>();
    gemm_mma<1><<<dim3(HH / NT, MM / MT), 128>>>(nullptr, w_out, b_out, out);
}

// round 9
// speedup vs baseline: 1.1919x; 1.1919x over previous
#include <cuda_runtime.h>
#include <cuda_bf16.h>
#include <cstdint>

// Problem dims
#define BB 2
#define SS 2048
#define HH 1024
#define NH 16
#define DD 64
#define MM (BB * SS)       // 4096 rows
#define K3H (3 * HH)       // 3072

// GEMM tiling: 128x128 CTA, 8 warps, 64x32 warp tile (R7 config)
#define MT 128
#define NT 128
#define KC 16
#define NCHUNK (HH / KC)   // 64
#define LDS_PAD 20

// Scratch (device globals; no allocation allowed)
__device__ float g_x [MM * HH];            // tf32-rounded hidden_states
__device__ float g_wi[K3H * HH];           // tf32-rounded w_in
__device__ float g_wo[HH * HH];            // tf32-rounded w_out
__device__ float g_q[BB * NH * SS * DD];   // [b][n][s][d], scaled, tf32-rounded
__device__ float g_k[BB * NH * SS * DD];   // [b][n][s][d], tf32-rounded
__device__ float g_v[BB * NH * DD * SS];   // [b][n][d][s], tf32-rounded
__device__ float g_o[MM * HH];             // [b*s][h], tf32-rounded

__device__ __forceinline__ uint32_t f2tf32(float x) {
    uint32_t r;
    asm("cvt.rna.tf32.f32 %0, %1;" : "=r"(r) : "f"(x));
    return r;
}
__device__ __forceinline__ float tf32f(float x) { return __uint_as_float(f2tf32(x)); }

__device__ __forceinline__ void mma_tf32(float* d, const uint32_t* a, const uint32_t* b) {
    asm volatile(
        "mma.sync.aligned.m16n8k8.row.col.f32.tf32.tf32.f32 "
        "{%0,%1,%2,%3}, {%4,%5,%6,%7}, {%8,%9}, {%0,%1,%2,%3};"
        : "+f"(d[0]), "+f"(d[1]), "+f"(d[2]), "+f"(d[3])
        : "r"(a[0]), "r"(a[1]), "r"(a[2]), "r"(a[3]), "r"(b[0]), "r"(b[1]));
}

__device__ __forceinline__ void ldsm4(uint32_t* r, const void* p) {
    uint32_t a = (uint32_t)__cvta_generic_to_shared(p);
    asm volatile("ldmatrix.sync.aligned.m8n8.x4.shared.b16 {%0,%1,%2,%3}, [%4];"
                 : "=r"(r[0]), "=r"(r[1]), "=r"(r[2]), "=r"(r[3]) : "r"(a));
}

__device__ __forceinline__ void cp_async16(void* smem_dst, const void* gsrc) {
    uint32_t a = (uint32_t)__cvta_generic_to_shared(smem_dst);
    asm volatile("cp.async.ca.shared.global [%0], [%1], 16;" :: "r"(a), "l"(gsrc));
}
#define CP_COMMIT() asm volatile("cp.async.commit_group;" ::: "memory")
#define CP_WAIT(n)  asm volatile("cp.async.wait_group %0;" :: "n"(n) : "memory")

// ---------------------------------------------------------------------------
// Pre-round pass: out[i] = tf32(in[i]) for hs / w_in / w_out
// ---------------------------------------------------------------------------
template <int WHICH>
__global__ void round_pass(const float4* __restrict__ in) {
    float* outp = (WHICH == 0) ? g_x : ((WHICH == 1) ? g_wi : g_wo);
    const int i = blockIdx.x * blockDim.x + threadIdx.x;
    float4 v = in[i];
    float4 w = make_float4(tf32f(v.x), tf32f(v.y), tf32f(v.z), tf32f(v.w));
    *(float4*)(outp + (long)i * 4) = w;
}

// ---------------------------------------------------------------------------
// tf32 mma.sync GEMM, 64x32 warp tiles, cp.async double-buffered mainloop.
// Inputs are pre-rounded tf32 -> no conversions in the loop.
// MODE 0: A=g_x, B=g_wi; scatter epilogue -> g_q/g_k (s-major), g_v (d-major).
// MODE 1: A=g_o, B=g_wo; Y = C + bias (fp32 out).
// ---------------------------------------------------------------------------
template <int MODE>
__global__ void __launch_bounds__(256)
gemm_mma(const float* __restrict__ bias, float* __restrict__ Y)
{
    __shared__ float Asm[2][MT][LDS_PAD];
    __shared__ float Bsm[2][NT][LDS_PAD];

    const float* Aptr = (MODE == 1) ? (const float*)g_o : (const float*)g_x;
    const float* Bptr = (MODE == 1) ? (const float*)g_wo : (const float*)g_wi;

    const int t    = threadIdx.x;
    const int wid  = t >> 5;
    const int lane = t & 31;
    const int g    = lane >> 2;
    const int c    = lane & 3;
    const int wm   = (wid >> 2) * 64;
    const int wn   = (wid & 3) * 32;
    const int m0   = blockIdx.y * MT;
    const int n0   = blockIdx.x * NT;

    const int a_row = ((lane >> 3) & 1) * 8 + (lane & 7);
    const int a_kof = (lane >> 4) * 4;
    const int b_row = ((lane >> 4) & 1) * 8 + (lane & 7);
    const int b_kof = ((lane >> 3) & 1) * 4;

    const int lrow = t >> 1;
    const int lk   = (t & 1) * 8;
    const float* Ag = Aptr + (long)(m0 + lrow) * HH + lk;
    const float* Bg = Bptr + (long)(n0 + lrow) * HH + lk;

    float acc[4][4][4];
#pragma unroll
    for (int mi = 0; mi < 4; mi++)
#pragma unroll
        for (int ni = 0; ni < 4; ni++)
#pragma unroll
            for (int k = 0; k < 4; k++) acc[mi][ni][k] = 0.f;

    // prologue: chunk 0 -> stage 0
    cp_async16(&Asm[0][lrow][lk],     Ag);
    cp_async16(&Asm[0][lrow][lk + 4], Ag + 4);
    cp_async16(&Bsm[0][lrow][lk],     Bg);
    cp_async16(&Bsm[0][lrow][lk + 4], Bg + 4);
    CP_COMMIT();

#pragma unroll 1
    for (int kt = 0; kt < NCHUNK; kt++) {
        const int st = kt & 1;
        if (kt + 1 < NCHUNK) {
            const int sn = st ^ 1;
            const float* Agn = Ag + (kt + 1) * KC;
            const float* Bgn = Bg + (kt + 1) * KC;
            cp_async16(&Asm[sn][lrow][lk],     Agn);
            cp_async16(&Asm[sn][lrow][lk + 4], Agn + 4);
            cp_async16(&Bsm[sn][lrow][lk],     Bgn);
            cp_async16(&Bsm[sn][lrow][lk + 4], Bgn + 4);
            CP_COMMIT();
            CP_WAIT(1);
        } else {
            CP_WAIT(0);
        }
        __syncthreads();

#pragma unroll
        for (int ks = 0; ks < 2; ks++) {
            const int k0 = ks * 8;
            uint32_t af[4][4], bfp[2][4];
#pragma unroll
            for (int mi = 0; mi < 4; mi++)
                ldsm4(af[mi], &Asm[st][wm + mi * 16 + a_row][k0 + a_kof]);
            ldsm4(bfp[0], &Bsm[st][wn + b_row][k0 + b_kof]);
            ldsm4(bfp[1], &Bsm[st][wn + 16 + b_row][k0 + b_kof]);
#pragma unroll
            for (int mi = 0; mi < 4; mi++) {
                mma_tf32(acc[mi][0], af[mi], &bfp[0][0]);
                mma_tf32(acc[mi][1], af[mi], &bfp[0][2]);
                mma_tf32(acc[mi][2], af[mi], &bfp[1][0]);
                mma_tf32(acc[mi][3], af[mi], &bfp[1][2]);
            }
        }
        __syncthreads();
    }

    // Epilogue
#pragma unroll
    for (int ni = 0; ni < 4; ni++) {
        const int col = n0 + wn + ni * 8 + 2 * c;
        const float b0 = bias[col];
        const float b1 = bias[col + 1];
#pragma unroll
        for (int mi = 0; mi < 4; mi++) {
            const int r1 = m0 + wm + mi * 16 + g;
            const int r2 = r1 + 8;
            if (MODE == 0) {
                const int which = col >> 10;
                const int hn    = (col & 1023) >> 6;
                const int d     = col & 63;
                const float scale = (which == 0) ? 0.125f : 1.0f;
                const int bb1 = r1 >> 11, s1 = r1 & 2047;
                const int bb2 = r2 >> 11, s2 = r2 & 2047;
                // tf32-round at the producer (bit-identical to consumer-side rounding)
                float2 v1 = make_float2(tf32f((acc[mi][ni][0] + b0) * scale),
                                        tf32f((acc[mi][ni][1] + b1) * scale));
                float2 v2 = make_float2(tf32f((acc[mi][ni][2] + b0) * scale),
                                        tf32f((acc[mi][ni][3] + b1) * scale));
                if (which == 2) {
                    float* p1 = g_v + ((long)(bb1 * NH + hn) * DD + d) * SS + s1;
                    float* p2 = g_v + ((long)(bb2 * NH + hn) * DD + d) * SS + s2;
                    p1[0] = v1.x; p1[SS] = v1.y;
                    p2[0] = v2.x; p2[SS] = v2.y;
                } else {
                    float* dst0 = (which == 0) ? g_q : g_k;
                    *(float2*)(dst0 + (((long)(bb1 * NH + hn) * SS) + s1) * DD + d) = v1;
                    *(float2*)(dst0 + (((long)(bb2 * NH + hn) * SS) + s2) * DD + d) = v2;
                }
            } else {
                float2 v1 = make_float2(acc[mi][ni][0] + b0, acc[mi][ni][1] + b1);
                float2 v2 = make_float2(acc[mi][ni][2] + b0, acc[mi][ni][3] + b1);
                *(float2*)(Y + (long)r1 * HH + col) = v1;
                *(float2*)(Y + (long)r2 * HH + col) = v2;
            }
        }
    }
}

// ---------------------------------------------------------------------------
// Kernel 2: causal flash attention, tf32 mma.sync + ldmatrix + LDG prefetch.
// All inputs pre-rounded tf32 -> no conversions in the loop.
// ---------------------------------------------------------------------------
__global__ __launch_bounds__(256) void flash_attn_mma()
{
    __shared__ float Ks[32][68];    // [kv][d]
    __shared__ float Vs[64][36];    // [d][kv]
    __shared__ float Ps[128][36];   // [qrow][kv]

    const int t    = threadIdx.x;
    const int wid  = t >> 5;
    const int lane = t & 31;
    const int g    = lane >> 2;
    const int c    = lane & 3;
    const int bn   = blockIdx.y;        // b*16+n
    const int q0   = blockIdx.x * 128;
    const int wr   = wid * 16;

    const int a_row = ((lane >> 3) & 1) * 8 + (lane & 7);
    const int a_kof = (lane >> 4) * 4;
    const int b_row = ((lane >> 4) & 1) * 8 + (lane & 7);
    const int b_kof = ((lane >> 3) & 1) * 4;

    const float* Qp = g_q + (long)bn * SS * DD;
    const float* Kp = g_k + (long)bn * SS * DD;
    const float* Vp = g_v + (long)bn * DD * SS;   // [d][s]

    const int k_row0 = t >> 4;
    const int k_c4   = (t & 15) * 4;
    const int v_row0 = t >> 3;
    const int v_s4   = (t & 7) * 4;

    // Q fragments (pre-rounded tf32: load bits directly)
    uint32_t Qf[8][4];
    {
        const float* qr0 = Qp + (long)(q0 + wr + g) * DD;
        const float* qr1 = qr0 + 8 * DD;
#pragma unroll
        for (int kc = 0; kc < 8; kc++) {
            Qf[kc][0] = __float_as_uint(qr0[kc * 8 + c]);
            Qf[kc][1] = __float_as_uint(qr1[kc * 8 + c]);
            Qf[kc][2] = __float_as_uint(qr0[kc * 8 + c + 4]);
            Qf[kc][3] = __float_as_uint(qr1[kc * 8 + c + 4]);
        }
    }

    float O[8][4];
#pragma unroll
    for (int dn = 0; dn < 8; dn++)
#pragma unroll
        for (int k = 0; k < 4; k++) O[dn][k] = 0.f;
    float m0v = -1e30f, m1v = -1e30f, l0 = 0.f, l1 = 0.f;

    const int r0g = q0 + wr + g;
    const int r1g = r0g + 8;
    const int nkt = (q0 + 128) >> 5;

    // prologue: prefetch tile 0
    float4 ka[2], va[2];
#pragma unroll
    for (int p = 0; p < 2; p++) {
        ka[p] = *(const float4*)(Kp + (long)(k_row0 + p * 16) * DD + k_c4);
        va[p] = *(const float4*)(Vp + (long)(v_row0 + p * 32) * SS + v_s4);
    }

    for (int kt = 0; kt < nkt; kt++) {
        const int k0 = kt * 32;
        __syncthreads();
#pragma unroll
        for (int p = 0; p < 2; p++) {
            *(float4*)&Ks[k_row0 + p * 16][k_c4] = ka[p];
            *(float4*)&Vs[v_row0 + p * 32][v_s4] = va[p];
        }
        __syncthreads();

        if (kt + 1 < nkt) {
            const int kn = k0 + 32;
#pragma unroll
            for (int p = 0; p < 2; p++) {
                ka[p] = *(const float4*)(Kp + (long)(kn + k_row0 + p * 16) * DD + k_c4);
                va[p] = *(const float4*)(Vp + (long)(v_row0 + p * 32) * SS + kn + v_s4);
            }
        }

        // S = Q K^T
        float S[4][4];
#pragma unroll
        for (int ni = 0; ni < 4; ni++)
#pragma unroll
            for (int k = 0; k < 4; k++) S[ni][k] = 0.f;
#pragma unroll
        for (int kc = 0; kc < 8; kc++) {
            uint32_t bt[4];
            ldsm4(bt, &Ks[b_row][kc * 8 + b_kof]);
            mma_tf32(S[0], Qf[kc], &bt[0]);
            mma_tf32(S[1], Qf[kc], &bt[2]);
            ldsm4(bt, &Ks[16 + b_row][kc * 8 + b_kof]);
            mma_tf32(S[2], Qf[kc], &bt[0]);
            mma_tf32(S[3], Qf[kc], &bt[2]);
        }

        // causal mask + row max
        float mx0 = m0v, mx1 = m1v;
#pragma unroll
        for (int ni = 0; ni < 4; ni++) {
            const int col0 = k0 + ni * 8 + 2 * c;
            const int col1 = col0 + 1;
            if (col0 > r0g) S[ni][0] = -1e30f;
            if (col1 > r0g) S[ni][1] = -1e30f;
            if (col0 > r1g) S[ni][2] = -1e30f;
            if (col1 > r1g) S[ni][3] = -1e30f;
            mx0 = fmaxf(mx0, fmaxf(S[ni][0], S[ni][1]));
            mx1 = fmaxf(mx1, fmaxf(S[ni][2], S[ni][3]));
        }
        mx0 = fmaxf(mx0, __shfl_xor_sync(0xffffffffu, mx0, 1));
        mx0 = fmaxf(mx0, __shfl_xor_sync(0xffffffffu, mx0, 2));
        mx1 = fmaxf(mx1, __shfl_xor_sync(0xffffffffu, mx1, 1));
        mx1 = fmaxf(mx1, __shfl_xor_sync(0xffffffffu, mx1, 2));

        const float a0 = __expf(m0v - mx0);
        const float a1 = __expf(m1v - mx1);
        m0v = mx0; m1v = mx1;

        float rs0 = 0.f, rs1 = 0.f;
#pragma unroll
        for (int ni = 0; ni < 4; ni++) {
            float p00 = __expf(S[ni][0] - mx0);
            float p01 = __expf(S[ni][1] - mx0);
            float p10 = __expf(S[ni][2] - mx1);
            float p11 = __expf(S[ni][3] - mx1);
            rs0 += p00 + p01; rs1 += p10 + p11;
            *(float2*)&Ps[wr + g][ni * 8 + 2 * c]     = make_float2(tf32f(p00), tf32f(p01));
            *(float2*)&Ps[wr + g + 8][ni * 8 + 2 * c] = make_float2(tf32f(p10), tf32f(p11));
        }
        rs0 += __shfl_xor_sync(0xffffffffu, rs0, 1);
        rs0 += __shfl_xor_sync(0xffffffffu, rs0, 2);
        rs1 += __shfl_xor_sync(0xffffffffu, rs1, 1);
        rs1 += __shfl_xor_sync(0xffffffffu, rs1, 2);
        l0 = l0 * a0 + rs0;
        l1 = l1 * a1 + rs1;

#pragma unroll
        for (int dn = 0; dn < 8; dn++) {
            O[dn][0] *= a0; O[dn][1] *= a0;
            O[dn][2] *= a1; O[dn][3] *= a1;
        }
        __syncwarp();

        // O += P @ V
#pragma unroll
        for (int j = 0; j < 4; j++) {
            uint32_t Af[4];
            ldsm4(Af, &Ps[wr + a_row][j * 8 + a_kof]);
#pragma unroll
            for (int dnp = 0; dnp < 4; dnp++) {
                uint32_t bt[4];
                ldsm4(bt, &Vs[dnp * 16 + b_row][j * 8 + b_kof]);
                mma_tf32(O[dnp * 2 + 0], Af, &bt[0]);
                mma_tf32(O[dnp * 2 + 1], Af, &bt[2]);
            }
        }
    }

    // epilogue: O /= l, tf32-round, write g_o[b*s][hn*64+d]
    const float inv0 = 1.0f / l0;
    const float inv1 = 1.0f / l1;
    const int b  = bn >> 4;
    const int hn = bn & 15;
    float* orow0 = g_o + (long)(b * SS + r0g) * HH + hn * DD;
    float* orow1 = orow0 + 8 * HH;
#pragma unroll
    for (int dn = 0; dn < 8; dn++) {
        *(float2*)(orow0 + dn * 8 + 2 * c) =
            make_float2(tf32f(O[dn][0] * inv0), tf32f(O[dn][1] * inv0));
        *(float2*)(orow1 + dn * 8 + 2 * c) =
            make_float2(tf32f(O[dn][2] * inv1), tf32f(O[dn][3] * inv1));
    }
}

// ---------------------------------------------------------------------------
extern "C" void kernel_launch(void* const* d_in, const int* in_sizes, int n_in,
                              void* d_out, int out_size)
{
    const float* hs    = (const float*)d_in[0];  // [B,S,H]
    const float* b_in  = (const float*)d_in[2];  // [3H]
    const float* w_in  = (const float*)d_in[1];  // [3H,H]
    const float* w_out = (const float*)d_in[3];  // [H,H]
    const float* b_out = (const float*)d_in[4];  // [H]
    float* out = (float*)d_out;                  // [B,S,H]

    (void)in_sizes; (void)n_in; (void)out_size;

    round_pass<0><<<(MM * HH) / 4 / 256, 256>>>((const float4*)hs);
    round_pass<1><<<(K3H * HH) / 4 / 256, 256>>>((const float4*)w_in);
    round_pass<2><<<(HH * HH) / 4 / 256, 256>>>((const float4*)w_out);

    gemm_mma<0><<<dim3(K3H / NT, MM / MT), 256>>>(b_in, nullptr);
    flash_attn_mma<<<dim3(SS / 128, BB * NH), 256>>>();
    gemm_mma<1><<<dim3(HH / NT, MM / MT), 256>>>(b_out, out);
}

// round 10
// speedup vs baseline: 1.2185x; 1.0224x over previous
#include <cuda_runtime.h>
#include <cuda_bf16.h>
#include <cstdint>

// Problem dims
#define BB 2
#define SS 2048
#define HH 1024
#define NH 16
#define DD 64
#define MM (BB * SS)       // 4096 rows
#define K3H (3 * HH)       // 3072

// GEMM tiling: 128x128 CTA, 8 warps, 64x32 warp tile, 3-stage cp.async
#define MT 128
#define NT 128
#define KC 16
#define NCHUNK (HH / KC)   // 64
#define NSTAGE 3

// Scratch (device globals; no allocation allowed)
__device__ float g_x [MM * HH];            // tf32-rounded hidden_states
__device__ float g_wi[K3H * HH];           // tf32-rounded w_in
__device__ float g_wo[HH * HH];            // tf32-rounded w_out
__device__ float g_q[BB * NH * SS * DD];   // [b][n][s][d], scaled, tf32-rounded
__device__ float g_k[BB * NH * SS * DD];   // [b][n][s][d], tf32-rounded
__device__ float g_v[BB * NH * DD * SS];   // [b][n][d][s], tf32-rounded
__device__ float g_o[MM * HH];             // [b*s][h], tf32-rounded

__device__ __forceinline__ uint32_t f2tf32(float x) {
    uint32_t r;
    asm("cvt.rna.tf32.f32 %0, %1;" : "=r"(r) : "f"(x));
    return r;
}
__device__ __forceinline__ float tf32f(float x) { return __uint_as_float(f2tf32(x)); }

__device__ __forceinline__ void mma_tf32(float* d, const uint32_t* a, const uint32_t* b) {
    asm volatile(
        "mma.sync.aligned.m16n8k8.row.col.f32.tf32.tf32.f32 "
        "{%0,%1,%2,%3}, {%4,%5,%6,%7}, {%8,%9}, {%0,%1,%2,%3};"
        : "+f"(d[0]), "+f"(d[1]), "+f"(d[2]), "+f"(d[3])
        : "r"(a[0]), "r"(a[1]), "r"(a[2]), "r"(a[3]), "r"(b[0]), "r"(b[1]));
}

__device__ __forceinline__ void ldsm4(uint32_t* r, const void* p) {
    uint32_t a = (uint32_t)__cvta_generic_to_shared(p);
    asm volatile("ldmatrix.sync.aligned.m8n8.x4.shared.b16 {%0,%1,%2,%3}, [%4];"
                 : "=r"(r[0]), "=r"(r[1]), "=r"(r[2]), "=r"(r[3]) : "r"(a));
}

__device__ __forceinline__ void cp_async16(void* smem_dst, const void* gsrc) {
    uint32_t a = (uint32_t)__cvta_generic_to_shared(smem_dst);
    asm volatile("cp.async.ca.shared.global [%0], [%1], 16;" :: "r"(a), "l"(gsrc));
}
#define CP_COMMIT() asm volatile("cp.async.commit_group;" ::: "memory")
#define CP_WAIT(n)  asm volatile("cp.async.wait_group %0;" :: "n"(n) : "memory")

// ---------------------------------------------------------------------------
// Pre-round pass: out[i] = tf32(in[i]) for hs / w_in / w_out
// ---------------------------------------------------------------------------
template <int WHICH>
__global__ void round_pass(const float4* __restrict__ in) {
    float* outp = (WHICH == 0) ? g_x : ((WHICH == 1) ? g_wi : g_wo);
    const int i = blockIdx.x * blockDim.x + threadIdx.x;
    float4 v = in[i];
    float4 w = make_float4(tf32f(v.x), tf32f(v.y), tf32f(v.z), tf32f(v.w));
    *(float4*)(outp + (long)i * 4) = w;
}

// ---------------------------------------------------------------------------
// tf32 mma.sync GEMM, 64x32 warp tiles, 3-stage cp.async, XOR-swizzled SMEM
// tiles ([128][16] floats, q' = q ^ ((row>>1)&3) on 16B units).
// One __syncthreads per k-chunk.
// MODE 0: A=g_x, B=g_wi; scatter epilogue -> g_q/g_k (s-major), g_v (d-major).
// MODE 1: A=g_o, B=g_wo; Y = C + bias (fp32 out).
// ---------------------------------------------------------------------------
template <int MODE>
__global__ void __launch_bounds__(256)
gemm_mma(const float* __restrict__ bias, float* __restrict__ Y)
{
    __shared__ float Asm[NSTAGE][MT][16];   // 24KB
    __shared__ float Bsm[NSTAGE][NT][16];   // 24KB  (total 48KB exactly)

    const float* Aptr = (MODE == 1) ? (const float*)g_o : (const float*)g_x;
    const float* Bptr = (MODE == 1) ? (const float*)g_wo : (const float*)g_wi;

    const int t    = threadIdx.x;
    const int wid  = t >> 5;
    const int lane = t & 31;
    const int g    = lane >> 2;
    const int c    = lane & 3;
    const int wm   = (wid >> 2) * 64;
    const int wn   = (wid & 3) * 32;
    const int m0   = blockIdx.y * MT;
    const int n0   = blockIdx.x * NT;

    // ldmatrix per-thread row / q(16B-unit) mapping
    const int a_row = ((lane >> 3) & 1) * 8 + (lane & 7);
    const int a_q   = lane >> 4;                 // 0/1
    const int a_swb = (a_row >> 1) & 3;          // swizzle base (tile-base invariant)
    const int b_row = ((lane >> 4) & 1) * 8 + (lane & 7);
    const int b_q   = (lane >> 3) & 1;
    const int b_swb = (b_row >> 1) & 3;

    // cp.async store mapping: row = t>>1, two 16B units q0=(t&1)*2, q0+1
    const int lrow = t >> 1;
    const int q0w  = (t & 1) * 2;
    const int sw0  = q0w ^ ((lrow >> 1) & 3);
    const int sw1  = (q0w + 1) ^ ((lrow >> 1) & 3);
    const float* Ag = Aptr + (long)(m0 + lrow) * HH + q0w * 4;
    const float* Bg = Bptr + (long)(n0 + lrow) * HH + q0w * 4;

    float acc[4][4][4];
#pragma unroll
    for (int mi = 0; mi < 4; mi++)
#pragma unroll
        for (int ni = 0; ni < 4; ni++)
#pragma unroll
            for (int k = 0; k < 4; k++) acc[mi][ni][k] = 0.f;

    // prologue: stage 0 and 1
#pragma unroll
    for (int s = 0; s < 2; s++) {
        const float* Ags = Ag + s * KC;
        const float* Bgs = Bg + s * KC;
        cp_async16(&Asm[s][lrow][sw0 * 4], Ags);
        cp_async16(&Asm[s][lrow][sw1 * 4], Ags + 4);
        cp_async16(&Bsm[s][lrow][sw0 * 4], Bgs);
        cp_async16(&Bsm[s][lrow][sw1 * 4], Bgs + 4);
        CP_COMMIT();
    }

    int st = 0, sf = 2;   // compute stage, fill stage
#pragma unroll 1
    for (int kt = 0; kt < NCHUNK; kt++) {
        CP_WAIT(1);              // chunk kt resident
        __syncthreads();         // + all warps done with stage sf (chunk kt-1's read of it was kt-1... stage sf was read in chunk kt-3)

        if (kt + 2 < NCHUNK) {   // issue chunk kt+2 into stage sf
            const float* Agn = Ag + (kt + 2) * KC;
            const float* Bgn = Bg + (kt + 2) * KC;
            cp_async16(&Asm[sf][lrow][sw0 * 4], Agn);
            cp_async16(&Asm[sf][lrow][sw1 * 4], Agn + 4);
            cp_async16(&Bsm[sf][lrow][sw0 * 4], Bgn);
            cp_async16(&Bsm[sf][lrow][sw1 * 4], Bgn + 4);
            CP_COMMIT();
        }

        // compute on stage st
#pragma unroll
        for (int ks = 0; ks < 2; ks++) {
            const int qa = (2 * ks + a_q) ^ a_swb;
            const int qb = (2 * ks + b_q) ^ b_swb;
            uint32_t af[4][4], bfp[2][4];
#pragma unroll
            for (int mi = 0; mi < 4; mi++)
                ldsm4(af[mi], &Asm[st][wm + mi * 16 + a_row][qa * 4]);
            ldsm4(bfp[0], &Bsm[st][wn + b_row][qb * 4]);
            ldsm4(bfp[1], &Bsm[st][wn + 16 + b_row][qb * 4]);
#pragma unroll
            for (int mi = 0; mi < 4; mi++) {
                mma_tf32(acc[mi][0], af[mi], &bfp[0][0]);
                mma_tf32(acc[mi][1], af[mi], &bfp[0][2]);
                mma_tf32(acc[mi][2], af[mi], &bfp[1][0]);
                mma_tf32(acc[mi][3], af[mi], &bfp[1][2]);
            }
        }
        st = (st == NSTAGE - 1) ? 0 : st + 1;
        sf = (sf == NSTAGE - 1) ? 0 : sf + 1;
    }

    // Epilogue
#pragma unroll
    for (int ni = 0; ni < 4; ni++) {
        const int col = n0 + wn + ni * 8 + 2 * c;
        const float b0 = bias[col];
        const float b1 = bias[col + 1];
#pragma unroll
        for (int mi = 0; mi < 4; mi++) {
            const int r1 = m0 + wm + mi * 16 + g;
            const int r2 = r1 + 8;
            if (MODE == 0) {
                const int which = col >> 10;
                const int hn    = (col & 1023) >> 6;
                const int d     = col & 63;
                const float scale = (which == 0) ? 0.125f : 1.0f;
                const int bb1 = r1 >> 11, s1 = r1 & 2047;
                const int bb2 = r2 >> 11, s2 = r2 & 2047;
                float2 v1 = make_float2(tf32f((acc[mi][ni][0] + b0) * scale),
                                        tf32f((acc[mi][ni][1] + b1) * scale));
                float2 v2 = make_float2(tf32f((acc[mi][ni][2] + b0) * scale),
                                        tf32f((acc[mi][ni][3] + b1) * scale));
                if (which == 2) {
                    float* p1 = g_v + ((long)(bb1 * NH + hn) * DD + d) * SS + s1;
                    float* p2 = g_v + ((long)(bb2 * NH + hn) * DD + d) * SS + s2;
                    p1[0] = v1.x; p1[SS] = v1.y;
                    p2[0] = v2.x; p2[SS] = v2.y;
                } else {
                    float* dst0 = (which == 0) ? g_q : g_k;
                    *(float2*)(dst0 + (((long)(bb1 * NH + hn) * SS) + s1) * DD + d) = v1;
                    *(float2*)(dst0 + (((long)(bb2 * NH + hn) * SS) + s2) * DD + d) = v2;
                }
            } else {
                float2 v1 = make_float2(acc[mi][ni][0] + b0, acc[mi][ni][1] + b1);
                float2 v2 = make_float2(acc[mi][ni][2] + b0, acc[mi][ni][3] + b1);
                *(float2*)(Y + (long)r1 * HH + col) = v1;
                *(float2*)(Y + (long)r2 * HH + col) = v2;
            }
        }
    }
}

// ---------------------------------------------------------------------------
// Kernel 2: causal flash attention (unchanged from R9 / known-good)
// ---------------------------------------------------------------------------
__global__ __launch_bounds__(256) void flash_attn_mma()
{
    __shared__ float Ks[32][68];    // [kv][d]
    __shared__ float Vs[64][36];    // [d][kv]
    __shared__ float Ps[128][36];   // [qrow][kv]

    const int t    = threadIdx.x;
    const int wid  = t >> 5;
    const int lane = t & 31;
    const int g    = lane >> 2;
    const int c    = lane & 3;
    const int bn   = blockIdx.y;        // b*16+n
    const int q0   = blockIdx.x * 128;
    const int wr   = wid * 16;

    const int a_row = ((lane >> 3) & 1) * 8 + (lane & 7);
    const int a_kof = (lane >> 4) * 4;
    const int b_row = ((lane >> 4) & 1) * 8 + (lane & 7);
    const int b_kof = ((lane >> 3) & 1) * 4;

    const float* Qp = g_q + (long)bn * SS * DD;
    const float* Kp = g_k + (long)bn * SS * DD;
    const float* Vp = g_v + (long)bn * DD * SS;   // [d][s]

    const int k_row0 = t >> 4;
    const int k_c4   = (t & 15) * 4;
    const int v_row0 = t >> 3;
    const int v_s4   = (t & 7) * 4;

    uint32_t Qf[8][4];
    {
        const float* qr0 = Qp + (long)(q0 + wr + g) * DD;
        const float* qr1 = qr0 + 8 * DD;
#pragma unroll
        for (int kc = 0; kc < 8; kc++) {
            Qf[kc][0] = __float_as_uint(qr0[kc * 8 + c]);
            Qf[kc][1] = __float_as_uint(qr1[kc * 8 + c]);
            Qf[kc][2] = __float_as_uint(qr0[kc * 8 + c + 4]);
            Qf[kc][3] = __float_as_uint(qr1[kc * 8 + c + 4]);
        }
    }

    float O[8][4];
#pragma unroll
    for (int dn = 0; dn < 8; dn++)
#pragma unroll
        for (int k = 0; k < 4; k++) O[dn][k] = 0.f;
    float m0v = -1e30f, m1v = -1e30f, l0 = 0.f, l1 = 0.f;

    const int r0g = q0 + wr + g;
    const int r1g = r0g + 8;
    const int nkt = (q0 + 128) >> 5;

    float4 ka[2], va[2];
#pragma unroll
    for (int p = 0; p < 2; p++) {
        ka[p] = *(const float4*)(Kp + (long)(k_row0 + p * 16) * DD + k_c4);
        va[p] = *(const float4*)(Vp + (long)(v_row0 + p * 32) * SS + v_s4);
    }

    for (int kt = 0; kt < nkt; kt++) {
        const int k0 = kt * 32;
        __syncthreads();
#pragma unroll
        for (int p = 0; p < 2; p++) {
            *(float4*)&Ks[k_row0 + p * 16][k_c4] = ka[p];
            *(float4*)&Vs[v_row0 + p * 32][v_s4] = va[p];
        }
        __syncthreads();

        if (kt + 1 < nkt) {
            const int kn = k0 + 32;
#pragma unroll
            for (int p = 0; p < 2; p++) {
                ka[p] = *(const float4*)(Kp + (long)(kn + k_row0 + p * 16) * DD + k_c4);
                va[p] = *(const float4*)(Vp + (long)(v_row0 + p * 32) * SS + kn + v_s4);
            }
        }

        float S[4][4];
#pragma unroll
        for (int ni = 0; ni < 4; ni++)
#pragma unroll
            for (int k = 0; k < 4; k++) S[ni][k] = 0.f;
#pragma unroll
        for (int kc = 0; kc < 8; kc++) {
            uint32_t bt[4];
            ldsm4(bt, &Ks[b_row][kc * 8 + b_kof]);
            mma_tf32(S[0], Qf[kc], &bt[0]);
            mma_tf32(S[1], Qf[kc], &bt[2]);
            ldsm4(bt, &Ks[16 + b_row][kc * 8 + b_kof]);
            mma_tf32(S[2], Qf[kc], &bt[0]);
            mma_tf32(S[3], Qf[kc], &bt[2]);
        }

        float mx0 = m0v, mx1 = m1v;
#pragma unroll
        for (int ni = 0; ni < 4; ni++) {
            const int col0 = k0 + ni * 8 + 2 * c;
            const int col1 = col0 + 1;
            if (col0 > r0g) S[ni][0] = -1e30f;
            if (col1 > r0g) S[ni][1] = -1e30f;
            if (col0 > r1g) S[ni][2] = -1e30f;
            if (col1 > r1g) S[ni][3] = -1e30f;
            mx0 = fmaxf(mx0, fmaxf(S[ni][0], S[ni][1]));
            mx1 = fmaxf(mx1, fmaxf(S[ni][2], S[ni][3]));
        }
        mx0 = fmaxf(mx0, __shfl_xor_sync(0xffffffffu, mx0, 1));
        mx0 = fmaxf(mx0, __shfl_xor_sync(0xffffffffu, mx0, 2));
        mx1 = fmaxf(mx1, __shfl_xor_sync(0xffffffffu, mx1, 1));
        mx1 = fmaxf(mx1, __shfl_xor_sync(0xffffffffu, mx1, 2));

        const float a0 = __expf(m0v - mx0);
        const float a1 = __expf(m1v - mx1);
        m0v = mx0; m1v = mx1;

        float rs0 = 0.f, rs1 = 0.f;
#pragma unroll
        for (int ni = 0; ni < 4; ni++) {
            float p00 = __expf(S[ni][0] - mx0);
            float p01 = __expf(S[ni][1] - mx0);
            float p10 = __expf(S[ni][2] - mx1);
            float p11 = __expf(S[ni][3] - mx1);
            rs0 += p00 + p01; rs1 += p10 + p11;
            *(float2*)&Ps[wr + g][ni * 8 + 2 * c]     = make_float2(tf32f(p00), tf32f(p01));
            *(float2*)&Ps[wr + g + 8][ni * 8 + 2 * c] = make_float2(tf32f(p10), tf32f(p11));
        }
        rs0 += __shfl_xor_sync(0xffffffffu, rs0, 1);
        rs0 += __shfl_xor_sync(0xffffffffu, rs0, 2);
        rs1 += __shfl_xor_sync(0xffffffffu, rs1, 1);
        rs1 += __shfl_xor_sync(0xffffffffu, rs1, 2);
        l0 = l0 * a0 + rs0;
        l1 = l1 * a1 + rs1;

#pragma unroll
        for (int dn = 0; dn < 8; dn++) {
            O[dn][0] *= a0; O[dn][1] *= a0;
            O[dn][2] *= a1; O[dn][3] *= a1;
        }
        __syncwarp();

#pragma unroll
        for (int j = 0; j < 4; j++) {
            uint32_t Af[4];
            ldsm4(Af, &Ps[wr + a_row][j * 8 + a_kof]);
#pragma unroll
            for (int dnp = 0; dnp < 4; dnp++) {
                uint32_t bt[4];
                ldsm4(bt, &Vs[dnp * 16 + b_row][j * 8 + b_kof]);
                mma_tf32(O[dnp * 2 + 0], Af, &bt[0]);
                mma_tf32(O[dnp * 2 + 1], Af, &bt[2]);
            }
        }
    }

    const float inv0 = 1.0f / l0;
    const float inv1 = 1.0f / l1;
    const int b  = bn >> 4;
    const int hn = bn & 15;
    float* orow0 = g_o + (long)(b * SS + r0g) * HH + hn * DD;
    float* orow1 = orow0 + 8 * HH;
#pragma unroll
    for (int dn = 0; dn < 8; dn++) {
        *(float2*)(orow0 + dn * 8 + 2 * c) =
            make_float2(tf32f(O[dn][0] * inv0), tf32f(O[dn][1] * inv0));
        *(float2*)(orow1 + dn * 8 + 2 * c) =
            make_float2(tf32f(O[dn][2] * inv1), tf32f(O[dn][3] * inv1));
    }
}

// ---------------------------------------------------------------------------
extern "C" void kernel_launch(void* const* d_in, const int* in_sizes, int n_in,
                              void* d_out, int out_size)
{
    const float* hs    = (const float*)d_in[0];  // [B,S,H]
    const float* w_in  = (const float*)d_in[1];  // [3H,H]
    const float* b_in  = (const float*)d_in[2];  // [3H]
    const float* w_out = (const float*)d_in[3];  // [H,H]
    const float* b_out = (const float*)d_in[4];  // [H]
    float* out = (float*)d_out;                  // [B,S,H]

    (void)in_sizes; (void)n_in; (void)out_size;

    round_pass<0><<<(MM * HH) / 4 / 256, 256>>>((const float4*)hs);
    round_pass<1><<<(K3H * HH) / 4 / 256, 256>>>((const float4*)w_in);
    round_pass<2><<<(HH * HH) / 4 / 256, 256>>>((const float4*)w_out);

    gemm_mma<0><<<dim3(K3H / NT, MM / MT), 256>>>(b_in, nullptr);
    flash_attn_mma<<<dim3(SS / 128, BB * NH), 256>>>();
    gemm_mma<1><<<dim3(HH / NT, MM / MT), 256>>>(b_out, out);
}

// round 11
// speedup vs baseline: 1.2257x; 1.0059x over previous
#include <cuda_runtime.h>
#include <cuda_bf16.h>
#include <cstdint>

// Problem dims
#define BB 2
#define SS 2048
#define HH 1024
#define NH 16
#define DD 64
#define MM (BB * SS)       // 4096 rows
#define K3H (3 * HH)       // 3072

// GEMM tiling: 128x128 CTA, 8 warps, 64x32 warp tile, 3-stage cp.async
#define MT 128
#define NT 128
#define KC 16
#define NCHUNK (HH / KC)   // 64
#define NSTAGE 3

// Scratch (device globals; no allocation allowed)
__device__ float g_x [MM * HH];            // tf32-rounded hidden_states
__device__ float g_wi[K3H * HH];           // tf32-rounded w_in
__device__ float g_wo[HH * HH];            // tf32-rounded w_out
__device__ float g_q[BB * NH * SS * DD];   // [b][n][s][d], scaled, tf32-rounded
__device__ float g_k[BB * NH * SS * DD];   // [b][n][s][d], tf32-rounded
__device__ float g_v[BB * NH * DD * SS];   // [b][n][d][s], tf32-rounded
__device__ float g_o[MM * HH];             // [b*s][h], tf32-rounded

__device__ __forceinline__ uint32_t f2tf32(float x) {
    uint32_t r;
    asm("cvt.rna.tf32.f32 %0, %1;" : "=r"(r) : "f"(x));
    return r;
}
__device__ __forceinline__ float tf32f(float x) { return __uint_as_float(f2tf32(x)); }

__device__ __forceinline__ void mma_tf32(float* d, const uint32_t* a, const uint32_t* b) {
    asm volatile(
        "mma.sync.aligned.m16n8k8.row.col.f32.tf32.tf32.f32 "
        "{%0,%1,%2,%3}, {%4,%5,%6,%7}, {%8,%9}, {%0,%1,%2,%3};"
        : "+f"(d[0]), "+f"(d[1]), "+f"(d[2]), "+f"(d[3])
        : "r"(a[0]), "r"(a[1]), "r"(a[2]), "r"(a[3]), "r"(b[0]), "r"(b[1]));
}

__device__ __forceinline__ void ldsm4(uint32_t* r, const void* p) {
    uint32_t a = (uint32_t)__cvta_generic_to_shared(p);
    asm volatile("ldmatrix.sync.aligned.m8n8.x4.shared.b16 {%0,%1,%2,%3}, [%4];"
                 : "=r"(r[0]), "=r"(r[1]), "=r"(r[2]), "=r"(r[3]) : "r"(a));
}

// .cg: fill SMEM via L2, bypass L1 -> removes LDGSTS wavefronts from L1tex
__device__ __forceinline__ void cp_async16(void* smem_dst, const void* gsrc) {
    uint32_t a = (uint32_t)__cvta_generic_to_shared(smem_dst);
    asm volatile("cp.async.cg.shared.global [%0], [%1], 16;" :: "r"(a), "l"(gsrc));
}
#define CP_COMMIT() asm volatile("cp.async.commit_group;" ::: "memory")
#define CP_WAIT(n)  asm volatile("cp.async.wait_group %0;" :: "n"(n) : "memory")

// ---------------------------------------------------------------------------
// Fused pre-round pass: g_x/g_wi/g_wo = tf32(hs/w_in/w_out)
// ---------------------------------------------------------------------------
#define NX4  (MM * HH / 4)
#define NWI4 (K3H * HH / 4)
#define NWO4 (HH * HH / 4)
__global__ void round_all(const float4* __restrict__ hs,
                          const float4* __restrict__ wi,
                          const float4* __restrict__ wo)
{
    const int i = blockIdx.x * blockDim.x + threadIdx.x;
    const float4* src;
    float* dst;
    int off;
    if (i < NX4)              { src = hs; dst = g_x;  off = i; }
    else if (i < NX4 + NWI4)  { src = wi; dst = g_wi; off = i - NX4; }
    else                      { src = wo; dst = g_wo; off = i - NX4 - NWI4; }
    float4 v = src[off];
    float4 w = make_float4(tf32f(v.x), tf32f(v.y), tf32f(v.z), tf32f(v.w));
    *(float4*)(dst + (long)off * 4) = w;
}

// ---------------------------------------------------------------------------
// tf32 mma.sync GEMM, 64x32 warp tiles, 3-stage cp.async(.cg), XOR-swizzled
// [128][16] SMEM tiles. One __syncthreads per k-chunk.
// MODE 0: A=g_x, B=g_wi; scatter epilogue -> g_q/g_k (s-major), g_v (d-major).
// MODE 1: A=g_o, B=g_wo; Y = C + bias (fp32 out).
// ---------------------------------------------------------------------------
template <int MODE>
__global__ void __launch_bounds__(256)
gemm_mma(const float* __restrict__ bias, float* __restrict__ Y)
{
    __shared__ float Asm[NSTAGE][MT][16];   // 24KB
    __shared__ float Bsm[NSTAGE][NT][16];   // 24KB

    const float* Aptr = (MODE == 1) ? (const float*)g_o : (const float*)g_x;
    const float* Bptr = (MODE == 1) ? (const float*)g_wo : (const float*)g_wi;

    const int t    = threadIdx.x;
    const int wid  = t >> 5;
    const int lane = t & 31;
    const int g    = lane >> 2;
    const int c    = lane & 3;
    const int wm   = (wid >> 2) * 64;
    const int wn   = (wid & 3) * 32;
    const int m0   = blockIdx.y * MT;
    const int n0   = blockIdx.x * NT;

    const int a_row = ((lane >> 3) & 1) * 8 + (lane & 7);
    const int a_q   = lane >> 4;
    const int a_swb = (a_row >> 1) & 3;
    const int b_row = ((lane >> 4) & 1) * 8 + (lane & 7);
    const int b_q   = (lane >> 3) & 1;
    const int b_swb = (b_row >> 1) & 3;

    const int lrow = t >> 1;
    const int q0w  = (t & 1) * 2;
    const int sw0  = q0w ^ ((lrow >> 1) & 3);
    const int sw1  = (q0w + 1) ^ ((lrow >> 1) & 3);
    const float* Ag = Aptr + (long)(m0 + lrow) * HH + q0w * 4;
    const float* Bg = Bptr + (long)(n0 + lrow) * HH + q0w * 4;

    float acc[4][4][4];
#pragma unroll
    for (int mi = 0; mi < 4; mi++)
#pragma unroll
        for (int ni = 0; ni < 4; ni++)
#pragma unroll
            for (int k = 0; k < 4; k++) acc[mi][ni][k] = 0.f;

#pragma unroll
    for (int s = 0; s < 2; s++) {
        const float* Ags = Ag + s * KC;
        const float* Bgs = Bg + s * KC;
        cp_async16(&Asm[s][lrow][sw0 * 4], Ags);
        cp_async16(&Asm[s][lrow][sw1 * 4], Ags + 4);
        cp_async16(&Bsm[s][lrow][sw0 * 4], Bgs);
        cp_async16(&Bsm[s][lrow][sw1 * 4], Bgs + 4);
        CP_COMMIT();
    }

    int st = 0, sf = 2;
#pragma unroll 1
    for (int kt = 0; kt < NCHUNK; kt++) {
        CP_WAIT(1);
        __syncthreads();

        if (kt + 2 < NCHUNK) {
            const float* Agn = Ag + (kt + 2) * KC;
            const float* Bgn = Bg + (kt + 2) * KC;
            cp_async16(&Asm[sf][lrow][sw0 * 4], Agn);
            cp_async16(&Asm[sf][lrow][sw1 * 4], Agn + 4);
            cp_async16(&Bsm[sf][lrow][sw0 * 4], Bgn);
            cp_async16(&Bsm[sf][lrow][sw1 * 4], Bgn + 4);
            CP_COMMIT();
        }

#pragma unroll
        for (int ks = 0; ks < 2; ks++) {
            const int qa = (2 * ks + a_q) ^ a_swb;
            const int qb = (2 * ks + b_q) ^ b_swb;
            uint32_t af[4][4], bfp[2][4];
#pragma unroll
            for (int mi = 0; mi < 4; mi++)
                ldsm4(af[mi], &Asm[st][wm + mi * 16 + a_row][qa * 4]);
            ldsm4(bfp[0], &Bsm[st][wn + b_row][qb * 4]);
            ldsm4(bfp[1], &Bsm[st][wn + 16 + b_row][qb * 4]);
#pragma unroll
            for (int mi = 0; mi < 4; mi++) {
                mma_tf32(acc[mi][0], af[mi], &bfp[0][0]);
                mma_tf32(acc[mi][1], af[mi], &bfp[0][2]);
                mma_tf32(acc[mi][2], af[mi], &bfp[1][0]);
                mma_tf32(acc[mi][3], af[mi], &bfp[1][2]);
            }
        }
        st = (st == NSTAGE - 1) ? 0 : st + 1;
        sf = (sf == NSTAGE - 1) ? 0 : sf + 1;
    }

    // Epilogue
#pragma unroll
    for (int ni = 0; ni < 4; ni++) {
        const int col = n0 + wn + ni * 8 + 2 * c;
        const float b0 = bias[col];
        const float b1 = bias[col + 1];
#pragma unroll
        for (int mi = 0; mi < 4; mi++) {
            const int r1 = m0 + wm + mi * 16 + g;
            const int r2 = r1 + 8;
            if (MODE == 0) {
                const int which = col >> 10;
                const int hn    = (col & 1023) >> 6;
                const int d     = col & 63;
                const float scale = (which == 0) ? 0.125f : 1.0f;
                const int bb1 = r1 >> 11, s1 = r1 & 2047;
                const int bb2 = r2 >> 11, s2 = r2 & 2047;
                float2 v1 = make_float2(tf32f((acc[mi][ni][0] + b0) * scale),
                                        tf32f((acc[mi][ni][1] + b1) * scale));
                float2 v2 = make_float2(tf32f((acc[mi][ni][2] + b0) * scale),
                                        tf32f((acc[mi][ni][3] + b1) * scale));
                if (which == 2) {
                    float* p1 = g_v + ((long)(bb1 * NH + hn) * DD + d) * SS + s1;
                    float* p2 = g_v + ((long)(bb2 * NH + hn) * DD + d) * SS + s2;
                    p1[0] = v1.x; p1[SS] = v1.y;
                    p2[0] = v2.x; p2[SS] = v2.y;
                } else {
                    float* dst0 = (which == 0) ? g_q : g_k;
                    *(float2*)(dst0 + (((long)(bb1 * NH + hn) * SS) + s1) * DD + d) = v1;
                    *(float2*)(dst0 + (((long)(bb2 * NH + hn) * SS) + s2) * DD + d) = v2;
                }
            } else {
                float2 v1 = make_float2(acc[mi][ni][0] + b0, acc[mi][ni][1] + b1);
                float2 v2 = make_float2(acc[mi][ni][2] + b0, acc[mi][ni][3] + b1);
                *(float2*)(Y + (long)r1 * HH + col) = v1;
                *(float2*)(Y + (long)r2 * HH + col) = v2;
            }
        }
    }
}

// ---------------------------------------------------------------------------
// Kernel 2: causal flash attention. Heavy-first CTA order (reversed q0) to
// fix the causal-workload wave imbalance.
// ---------------------------------------------------------------------------
__global__ __launch_bounds__(256) void flash_attn_mma()
{
    __shared__ float Ks[32][68];    // [kv][d]
    __shared__ float Vs[64][36];    // [d][kv]
    __shared__ float Ps[128][36];   // [qrow][kv]

    const int t    = threadIdx.x;
    const int wid  = t >> 5;
    const int lane = t & 31;
    const int g    = lane >> 2;
    const int c    = lane & 3;
    const int bn   = blockIdx.y;        // b*16+n
    const int q0   = (gridDim.x - 1 - blockIdx.x) * 128;   // heavy tiles first
    const int wr   = wid * 16;

    const int a_row = ((lane >> 3) & 1) * 8 + (lane & 7);
    const int a_kof = (lane >> 4) * 4;
    const int b_row = ((lane >> 4) & 1) * 8 + (lane & 7);
    const int b_kof = ((lane >> 3) & 1) * 4;

    const float* Qp = g_q + (long)bn * SS * DD;
    const float* Kp = g_k + (long)bn * SS * DD;
    const float* Vp = g_v + (long)bn * DD * SS;   // [d][s]

    const int k_row0 = t >> 4;
    const int k_c4   = (t & 15) * 4;
    const int v_row0 = t >> 3;
    const int v_s4   = (t & 7) * 4;

    uint32_t Qf[8][4];
    {
        const float* qr0 = Qp + (long)(q0 + wr + g) * DD;
        const float* qr1 = qr0 + 8 * DD;
#pragma unroll
        for (int kc = 0; kc < 8; kc++) {
            Qf[kc][0] = __float_as_uint(qr0[kc * 8 + c]);
            Qf[kc][1] = __float_as_uint(qr1[kc * 8 + c]);
            Qf[kc][2] = __float_as_uint(qr0[kc * 8 + c + 4]);
            Qf[kc][3] = __float_as_uint(qr1[kc * 8 + c + 4]);
        }
    }

    float O[8][4];
#pragma unroll
    for (int dn = 0; dn < 8; dn++)
#pragma unroll
        for (int k = 0; k < 4; k++) O[dn][k] = 0.f;
    float m0v = -1e30f, m1v = -1e30f, l0 = 0.f, l1 = 0.f;

    const int r0g = q0 + wr + g;
    const int r1g = r0g + 8;
    const int nkt = (q0 + 128) >> 5;

    float4 ka[2], va[2];
#pragma unroll
    for (int p = 0; p < 2; p++) {
        ka[p] = *(const float4*)(Kp + (long)(k_row0 + p * 16) * DD + k_c4);
        va[p] = *(const float4*)(Vp + (long)(v_row0 + p * 32) * SS + v_s4);
    }

    for (int kt = 0; kt < nkt; kt++) {
        const int k0 = kt * 32;
        __syncthreads();
#pragma unroll
        for (int p = 0; p < 2; p++) {
            *(float4*)&Ks[k_row0 + p * 16][k_c4] = ka[p];
            *(float4*)&Vs[v_row0 + p * 32][v_s4] = va[p];
        }
        __syncthreads();

        if (kt + 1 < nkt) {
            const int kn = k0 + 32;
#pragma unroll
            for (int p = 0; p < 2; p++) {
                ka[p] = *(const float4*)(Kp + (long)(kn + k_row0 + p * 16) * DD + k_c4);
                va[p] = *(const float4*)(Vp + (long)(v_row0 + p * 32) * SS + kn + v_s4);
            }
        }

        float S[4][4];
#pragma unroll
        for (int ni = 0; ni < 4; ni++)
#pragma unroll
            for (int k = 0; k < 4; k++) S[ni][k] = 0.f;
#pragma unroll
        for (int kc = 0; kc < 8; kc++) {
            uint32_t bt[4];
            ldsm4(bt, &Ks[b_row][kc * 8 + b_kof]);
            mma_tf32(S[0], Qf[kc], &bt[0]);
            mma_tf32(S[1], Qf[kc], &bt[2]);
            ldsm4(bt, &Ks[16 + b_row][kc * 8 + b_kof]);
            mma_tf32(S[2], Qf[kc], &bt[0]);
            mma_tf32(S[3], Qf[kc], &bt[2]);
        }

        float mx0 = m0v, mx1 = m1v;
#pragma unroll
        for (int ni = 0; ni < 4; ni++) {
            const int col0 = k0 + ni * 8 + 2 * c;
            const int col1 = col0 + 1;
            if (col0 > r0g) S[ni][0] = -1e30f;
            if (col1 > r0g) S[ni][1] = -1e30f;
            if (col0 > r1g) S[ni][2] = -1e30f;
            if (col1 > r1g) S[ni][3] = -1e30f;
            mx0 = fmaxf(mx0, fmaxf(S[ni][0], S[ni][1]));
            mx1 = fmaxf(mx1, fmaxf(S[ni][2], S[ni][3]));
        }
        mx0 = fmaxf(mx0, __shfl_xor_sync(0xffffffffu, mx0, 1));
        mx0 = fmaxf(mx0, __shfl_xor_sync(0xffffffffu, mx0, 2));
        mx1 = fmaxf(mx1, __shfl_xor_sync(0xffffffffu, mx1, 1));
        mx1 = fmaxf(mx1, __shfl_xor_sync(0xffffffffu, mx1, 2));

        const float a0 = __expf(m0v - mx0);
        const float a1 = __expf(m1v - mx1);
        m0v = mx0; m1v = mx1;

        float rs0 = 0.f, rs1 = 0.f;
#pragma unroll
        for (int ni = 0; ni < 4; ni++) {
            float p00 = __expf(S[ni][0] - mx0);
            float p01 = __expf(S[ni][1] - mx0);
            float p10 = __expf(S[ni][2] - mx1);
            float p11 = __expf(S[ni][3] - mx1);
            rs0 += p00 + p01; rs1 += p10 + p11;
            *(float2*)&Ps[wr + g][ni * 8 + 2 * c]     = make_float2(tf32f(p00), tf32f(p01));
            *(float2*)&Ps[wr + g + 8][ni * 8 + 2 * c] = make_float2(tf32f(p10), tf32f(p11));
        }
        rs0 += __shfl_xor_sync(0xffffffffu, rs0, 1);
        rs0 += __shfl_xor_sync(0xffffffffu, rs0, 2);
        rs1 += __shfl_xor_sync(0xffffffffu, rs1, 1);
        rs1 += __shfl_xor_sync(0xffffffffu, rs1, 2);
        l0 = l0 * a0 + rs0;
        l1 = l1 * a1 + rs1;

#pragma unroll
        for (int dn = 0; dn < 8; dn++) {
            O[dn][0] *= a0; O[dn][1] *= a0;
            O[dn][2] *= a1; O[dn][3] *= a1;
        }
        __syncwarp();

#pragma unroll
        for (int j = 0; j < 4; j++) {
            uint32_t Af[4];
            ldsm4(Af, &Ps[wr + a_row][j * 8 + a_kof]);
#pragma unroll
            for (int dnp = 0; dnp < 4; dnp++) {
                uint32_t bt[4];
                ldsm4(bt, &Vs[dnp * 16 + b_row][j * 8 + b_kof]);
                mma_tf32(O[dnp * 2 + 0], Af, &bt[0]);
                mma_tf32(O[dnp * 2 + 1], Af, &bt[2]);
            }
        }
    }

    const float inv0 = 1.0f / l0;
    const float inv1 = 1.0f / l1;
    const int b  = bn >> 4;
    const int hn = bn & 15;
    float* orow0 = g_o + (long)(b * SS + r0g) * HH + hn * DD;
    float* orow1 = orow0 + 8 * HH;
#pragma unroll
    for (int dn = 0; dn < 8; dn++) {
        *(float2*)(orow0 + dn * 8 + 2 * c) =
            make_float2(tf32f(O[dn][0] * inv0), tf32f(O[dn][1] * inv0));
        *(float2*)(orow1 + dn * 8 + 2 * c) =
            make_float2(tf32f(O[dn][2] * inv1), tf32f(O[dn][3] * inv1));
    }
}

// ---------------------------------------------------------------------------
extern "C" void kernel_launch(void* const* d_in, const int* in_sizes, int n_in,
                              void* d_out, int out_size)
{
    const float* hs    = (const float*)d_in[0];  // [B,S,H]
    const float* w_in  = (const float*)d_in[1];  // [3H,H]
    const float* b_in  = (const float*)d_in[2];  // [3H]
    const float* w_out = (const float*)d_in[3];  // [H,H]
    const float* b_out = (const float*)d_in[4];  // [H]
    float* out = (float*)d_out;                  // [B,S,H]

    (void)in_sizes; (void)n_in; (void)out_size;

    round_all<<<(NX4 + NWI4 + NWO4) / 256, 256>>>(
        (const float4*)hs, (const float4*)w_in, (const float4*)w_out);

    gemm_mma<0><<<dim3(K3H / NT, MM / MT), 256>>>(b_in, nullptr);
    flash_attn_mma<<<dim3(SS / 128, BB * NH), 256>>>();
    gemm_mma<1><<<dim3(HH / NT, MM / MT), 256>>>(b_out, out);
}

// round 12
// speedup vs baseline: 1.2925x; 1.0545x over previous
#include <cuda_runtime.h>
#include <cuda_bf16.h>
#include <cstdint>

// Problem dims
#define BB 2
#define SS 2048
#define HH 1024
#define NH 16
#define DD 64
#define MM (BB * SS)       // 4096 rows
#define K3H (3 * HH)       // 3072

// GEMM tiling: 128x128 CTA, 8 warps, 64x32 warp tile, 3-stage cp.async
#define MT 128
#define NT 128
#define KC 16
#define NCHUNK (HH / KC)   // 64
#define NSTAGE 3

// Scratch (device globals; no allocation allowed)
__device__ float g_x [MM * HH];            // tf32-rounded hidden_states
__device__ float g_wi[K3H * HH];           // tf32-rounded w_in
__device__ float g_wo[HH * HH];            // tf32-rounded w_out
__device__ float g_q[BB * NH * SS * DD];   // [b][n][s][d], scaled, tf32-rounded
__device__ float g_k[BB * NH * SS * DD];   // [b][n][s][d], tf32-rounded
__device__ float g_v[BB * NH * DD * SS];   // [b][n][d][s], tf32-rounded
__device__ float g_o[MM * HH];             // [b*s][h], tf32-rounded

__device__ __forceinline__ uint32_t f2tf32(float x) {
    uint32_t r;
    asm("cvt.rna.tf32.f32 %0, %1;" : "=r"(r) : "f"(x));
    return r;
}
__device__ __forceinline__ float tf32f(float x) { return __uint_as_float(f2tf32(x)); }

__device__ __forceinline__ void mma_tf32(float* d, const uint32_t* a, const uint32_t* b) {
    asm volatile(
        "mma.sync.aligned.m16n8k8.row.col.f32.tf32.tf32.f32 "
        "{%0,%1,%2,%3}, {%4,%5,%6,%7}, {%8,%9}, {%0,%1,%2,%3};"
        : "+f"(d[0]), "+f"(d[1]), "+f"(d[2]), "+f"(d[3])
        : "r"(a[0]), "r"(a[1]), "r"(a[2]), "r"(a[3]), "r"(b[0]), "r"(b[1]));
}

__device__ __forceinline__ void ldsm4(uint32_t* r, const void* p) {
    uint32_t a = (uint32_t)__cvta_generic_to_shared(p);
    asm volatile("ldmatrix.sync.aligned.m8n8.x4.shared.b16 {%0,%1,%2,%3}, [%4];"
                 : "=r"(r[0]), "=r"(r[1]), "=r"(r[2]), "=r"(r[3]) : "r"(a));
}

// .cg: fill SMEM via L2, bypass L1
__device__ __forceinline__ void cp_async16(void* smem_dst, const void* gsrc) {
    uint32_t a = (uint32_t)__cvta_generic_to_shared(smem_dst);
    asm volatile("cp.async.cg.shared.global [%0], [%1], 16;" :: "r"(a), "l"(gsrc));
}
#define CP_COMMIT() asm volatile("cp.async.commit_group;" ::: "memory")
#define CP_WAIT(n)  asm volatile("cp.async.wait_group %0;" :: "n"(n) : "memory")

// ---------------------------------------------------------------------------
// Fused pre-round pass
// ---------------------------------------------------------------------------
#define NX4  (MM * HH / 4)
#define NWI4 (K3H * HH / 4)
#define NWO4 (HH * HH / 4)
__global__ void round_all(const float4* __restrict__ hs,
                          const float4* __restrict__ wi,
                          const float4* __restrict__ wo)
{
    const int i = blockIdx.x * blockDim.x + threadIdx.x;
    const float4* src;
    float* dst;
    int off;
    if (i < NX4)              { src = hs; dst = g_x;  off = i; }
    else if (i < NX4 + NWI4)  { src = wi; dst = g_wi; off = i - NX4; }
    else                      { src = wo; dst = g_wo; off = i - NX4 - NWI4; }
    float4 v = src[off];
    float4 w = make_float4(tf32f(v.x), tf32f(v.y), tf32f(v.z), tf32f(v.w));
    *(float4*)(dst + (long)off * 4) = w;
}

// ---------------------------------------------------------------------------
// tf32 mma.sync GEMM: 3-stage cp.async(.cg), XOR-swizzled [128][16] tiles,
// fragment-pipelined inner loop (all 12 LDSM up front, then 32 MMAs).
// ---------------------------------------------------------------------------
template <int MODE>
__global__ void __launch_bounds__(256, 2)
gemm_mma(const float* __restrict__ bias, float* __restrict__ Y)
{
    __shared__ float Asm[NSTAGE][MT][16];
    __shared__ float Bsm[NSTAGE][NT][16];

    const float* Aptr = (MODE == 1) ? (const float*)g_o : (const float*)g_x;
    const float* Bptr = (MODE == 1) ? (const float*)g_wo : (const float*)g_wi;

    const int t    = threadIdx.x;
    const int wid  = t >> 5;
    const int lane = t & 31;
    const int g    = lane >> 2;
    const int c    = lane & 3;
    const int wm   = (wid >> 2) * 64;
    const int wn   = (wid & 3) * 32;
    const int m0   = blockIdx.y * MT;
    const int n0   = blockIdx.x * NT;

    const int a_row = ((lane >> 3) & 1) * 8 + (lane & 7);
    const int a_q   = lane >> 4;
    const int a_swb = (a_row >> 1) & 3;
    const int b_row = ((lane >> 4) & 1) * 8 + (lane & 7);
    const int b_q   = (lane >> 3) & 1;
    const int b_swb = (b_row >> 1) & 3;

    const int lrow = t >> 1;
    const int q0w  = (t & 1) * 2;
    const int sw0  = q0w ^ ((lrow >> 1) & 3);
    const int sw1  = (q0w + 1) ^ ((lrow >> 1) & 3);
    const float* Ag = Aptr + (long)(m0 + lrow) * HH + q0w * 4;
    const float* Bg = Bptr + (long)(n0 + lrow) * HH + q0w * 4;

    float acc[4][4][4];
#pragma unroll
    for (int mi = 0; mi < 4; mi++)
#pragma unroll
        for (int ni = 0; ni < 4; ni++)
#pragma unroll
            for (int k = 0; k < 4; k++) acc[mi][ni][k] = 0.f;

#pragma unroll
    for (int s = 0; s < 2; s++) {
        const float* Ags = Ag + s * KC;
        const float* Bgs = Bg + s * KC;
        cp_async16(&Asm[s][lrow][sw0 * 4], Ags);
        cp_async16(&Asm[s][lrow][sw1 * 4], Ags + 4);
        cp_async16(&Bsm[s][lrow][sw0 * 4], Bgs);
        cp_async16(&Bsm[s][lrow][sw1 * 4], Bgs + 4);
        CP_COMMIT();
    }

    // per-ks swizzled q indices (constants per thread)
    const int qa0 = (0 + a_q) ^ a_swb, qa1 = (2 + a_q) ^ a_swb;
    const int qb0 = (0 + b_q) ^ b_swb, qb1 = (2 + b_q) ^ b_swb;

    int st = 0, sf = 2;
#pragma unroll 1
    for (int kt = 0; kt < NCHUNK; kt++) {
        CP_WAIT(1);
        __syncthreads();

        if (kt + 2 < NCHUNK) {
            const float* Agn = Ag + (kt + 2) * KC;
            const float* Bgn = Bg + (kt + 2) * KC;
            cp_async16(&Asm[sf][lrow][sw0 * 4], Agn);
            cp_async16(&Asm[sf][lrow][sw1 * 4], Agn + 4);
            cp_async16(&Bsm[sf][lrow][sw0 * 4], Bgn);
            cp_async16(&Bsm[sf][lrow][sw1 * 4], Bgn + 4);
            CP_COMMIT();
        }

        // ---- fragment-pipelined compute: all loads, then all MMAs ----
        uint32_t af[2][4][4], bfp[2][2][4];
#pragma unroll
        for (int mi = 0; mi < 4; mi++)
            ldsm4(af[0][mi], &Asm[st][wm + mi * 16 + a_row][qa0 * 4]);
        ldsm4(bfp[0][0], &Bsm[st][wn + b_row][qb0 * 4]);
        ldsm4(bfp[0][1], &Bsm[st][wn + 16 + b_row][qb0 * 4]);
#pragma unroll
        for (int mi = 0; mi < 4; mi++)
            ldsm4(af[1][mi], &Asm[st][wm + mi * 16 + a_row][qa1 * 4]);
        ldsm4(bfp[1][0], &Bsm[st][wn + b_row][qb1 * 4]);
        ldsm4(bfp[1][1], &Bsm[st][wn + 16 + b_row][qb1 * 4]);

#pragma unroll
        for (int ks = 0; ks < 2; ks++)
#pragma unroll
            for (int mi = 0; mi < 4; mi++) {
                mma_tf32(acc[mi][0], af[ks][mi], &bfp[ks][0][0]);
                mma_tf32(acc[mi][1], af[ks][mi], &bfp[ks][0][2]);
                mma_tf32(acc[mi][2], af[ks][mi], &bfp[ks][1][0]);
                mma_tf32(acc[mi][3], af[ks][mi], &bfp[ks][1][2]);
            }

        st = (st == NSTAGE - 1) ? 0 : st + 1;
        sf = (sf == NSTAGE - 1) ? 0 : sf + 1;
    }

    // Epilogue
#pragma unroll
    for (int ni = 0; ni < 4; ni++) {
        const int col = n0 + wn + ni * 8 + 2 * c;
        const float b0 = bias[col];
        const float b1 = bias[col + 1];
#pragma unroll
        for (int mi = 0; mi < 4; mi++) {
            const int r1 = m0 + wm + mi * 16 + g;
            const int r2 = r1 + 8;
            if (MODE == 0) {
                const int which = col >> 10;
                const int hn    = (col & 1023) >> 6;
                const int d     = col & 63;
                const float scale = (which == 0) ? 0.125f : 1.0f;
                const int bb1 = r1 >> 11, s1 = r1 & 2047;
                const int bb2 = r2 >> 11, s2 = r2 & 2047;
                float2 v1 = make_float2(tf32f((acc[mi][ni][0] + b0) * scale),
                                        tf32f((acc[mi][ni][1] + b1) * scale));
                float2 v2 = make_float2(tf32f((acc[mi][ni][2] + b0) * scale),
                                        tf32f((acc[mi][ni][3] + b1) * scale));
                if (which == 2) {
                    float* p1 = g_v + ((long)(bb1 * NH + hn) * DD + d) * SS + s1;
                    float* p2 = g_v + ((long)(bb2 * NH + hn) * DD + d) * SS + s2;
                    p1[0] = v1.x; p1[SS] = v1.y;
                    p2[0] = v2.x; p2[SS] = v2.y;
                } else {
                    float* dst0 = (which == 0) ? g_q : g_k;
                    *(float2*)(dst0 + (((long)(bb1 * NH + hn) * SS) + s1) * DD + d) = v1;
                    *(float2*)(dst0 + (((long)(bb2 * NH + hn) * SS) + s2) * DD + d) = v2;
                }
            } else {
                float2 v1 = make_float2(acc[mi][ni][0] + b0, acc[mi][ni][1] + b1);
                float2 v2 = make_float2(acc[mi][ni][2] + b0, acc[mi][ni][3] + b1);
                *(float2*)(Y + (long)r1 * HH + col) = v1;
                *(float2*)(Y + (long)r2 * HH + col) = v2;
            }
        }
    }
}

// ---------------------------------------------------------------------------
// Kernel 2: causal flash attention, heavy-first order, fragment-pipelined
// QK (K-frag prefetch) and PV (P-frag prefetch).
// ---------------------------------------------------------------------------
__global__ void __launch_bounds__(256, 2) flash_attn_mma()
{
    __shared__ float Ks[32][68];    // [kv][d]
    __shared__ float Vs[64][36];    // [d][kv]
    __shared__ float Ps[128][36];   // [qrow][kv]

    const int t    = threadIdx.x;
    const int wid  = t >> 5;
    const int lane = t & 31;
    const int g    = lane >> 2;
    const int c    = lane & 3;
    const int bn   = blockIdx.y;
    const int q0   = (gridDim.x - 1 - blockIdx.x) * 128;   // heavy tiles first
    const int wr   = wid * 16;

    const int a_row = ((lane >> 3) & 1) * 8 + (lane & 7);
    const int a_kof = (lane >> 4) * 4;
    const int b_row = ((lane >> 4) & 1) * 8 + (lane & 7);
    const int b_kof = ((lane >> 3) & 1) * 4;

    const float* Qp = g_q + (long)bn * SS * DD;
    const float* Kp = g_k + (long)bn * SS * DD;
    const float* Vp = g_v + (long)bn * DD * SS;

    const int k_row0 = t >> 4;
    const int k_c4   = (t & 15) * 4;
    const int v_row0 = t >> 3;
    const int v_s4   = (t & 7) * 4;

    uint32_t Qf[8][4];
    {
        const float* qr0 = Qp + (long)(q0 + wr + g) * DD;
        const float* qr1 = qr0 + 8 * DD;
#pragma unroll
        for (int kc = 0; kc < 8; kc++) {
            Qf[kc][0] = __float_as_uint(qr0[kc * 8 + c]);
            Qf[kc][1] = __float_as_uint(qr1[kc * 8 + c]);
            Qf[kc][2] = __float_as_uint(qr0[kc * 8 + c + 4]);
            Qf[kc][3] = __float_as_uint(qr1[kc * 8 + c + 4]);
        }
    }

    float O[8][4];
#pragma unroll
    for (int dn = 0; dn < 8; dn++)
#pragma unroll
        for (int k = 0; k < 4; k++) O[dn][k] = 0.f;
    float m0v = -1e30f, m1v = -1e30f, l0 = 0.f, l1 = 0.f;

    const int r0g = q0 + wr + g;
    const int r1g = r0g + 8;
    const int nkt = (q0 + 128) >> 5;

    float4 ka[2], va[2];
#pragma unroll
    for (int p = 0; p < 2; p++) {
        ka[p] = *(const float4*)(Kp + (long)(k_row0 + p * 16) * DD + k_c4);
        va[p] = *(const float4*)(Vp + (long)(v_row0 + p * 32) * SS + v_s4);
    }

    for (int kt = 0; kt < nkt; kt++) {
        const int k0 = kt * 32;
        __syncthreads();
#pragma unroll
        for (int p = 0; p < 2; p++) {
            *(float4*)&Ks[k_row0 + p * 16][k_c4] = ka[p];
            *(float4*)&Vs[v_row0 + p * 32][v_s4] = va[p];
        }
        __syncthreads();

        if (kt + 1 < nkt) {
            const int kn = k0 + 32;
#pragma unroll
            for (int p = 0; p < 2; p++) {
                ka[p] = *(const float4*)(Kp + (long)(kn + k_row0 + p * 16) * DD + k_c4);
                va[p] = *(const float4*)(Vp + (long)(v_row0 + p * 32) * SS + kn + v_s4);
            }
        }

        // ---- S = Q K^T, K-frag prefetch pipeline ----
        float S[4][4];
#pragma unroll
        for (int ni = 0; ni < 4; ni++)
#pragma unroll
            for (int k = 0; k < 4; k++) S[ni][k] = 0.f;

        uint32_t btA[4], btB[4];
        ldsm4(btA, &Ks[b_row][b_kof]);
        ldsm4(btB, &Ks[16 + b_row][b_kof]);
#pragma unroll
        for (int kc = 0; kc < 8; kc++) {
            uint32_t nA[4], nB[4];
            if (kc < 7) {
                ldsm4(nA, &Ks[b_row][(kc + 1) * 8 + b_kof]);
                ldsm4(nB, &Ks[16 + b_row][(kc + 1) * 8 + b_kof]);
            }
            mma_tf32(S[0], Qf[kc], &btA[0]);
            mma_tf32(S[1], Qf[kc], &btA[2]);
            mma_tf32(S[2], Qf[kc], &btB[0]);
            mma_tf32(S[3], Qf[kc], &btB[2]);
            if (kc < 7) {
#pragma unroll
                for (int z = 0; z < 4; z++) { btA[z] = nA[z]; btB[z] = nB[z]; }
            }
        }

        // causal mask + row max
        float mx0 = m0v, mx1 = m1v;
#pragma unroll
        for (int ni = 0; ni < 4; ni++) {
            const int col0 = k0 + ni * 8 + 2 * c;
            const int col1 = col0 + 1;
            if (col0 > r0g) S[ni][0] = -1e30f;
            if (col1 > r0g) S[ni][1] = -1e30f;
            if (col0 > r1g) S[ni][2] = -1e30f;
            if (col1 > r1g) S[ni][3] = -1e30f;
            mx0 = fmaxf(mx0, fmaxf(S[ni][0], S[ni][1]));
            mx1 = fmaxf(mx1, fmaxf(S[ni][2], S[ni][3]));
        }
        mx0 = fmaxf(mx0, __shfl_xor_sync(0xffffffffu, mx0, 1));
        mx0 = fmaxf(mx0, __shfl_xor_sync(0xffffffffu, mx0, 2));
        mx1 = fmaxf(mx1, __shfl_xor_sync(0xffffffffu, mx1, 1));
        mx1 = fmaxf(mx1, __shfl_xor_sync(0xffffffffu, mx1, 2));

        const float a0 = __expf(m0v - mx0);
        const float a1 = __expf(m1v - mx1);
        m0v = mx0; m1v = mx1;

        float rs0 = 0.f, rs1 = 0.f;
#pragma unroll
        for (int ni = 0; ni < 4; ni++) {
            float p00 = __expf(S[ni][0] - mx0);
            float p01 = __expf(S[ni][1] - mx0);
            float p10 = __expf(S[ni][2] - mx1);
            float p11 = __expf(S[ni][3] - mx1);
            rs0 += p00 + p01; rs1 += p10 + p11;
            *(float2*)&Ps[wr + g][ni * 8 + 2 * c]     = make_float2(tf32f(p00), tf32f(p01));
            *(float2*)&Ps[wr + g + 8][ni * 8 + 2 * c] = make_float2(tf32f(p10), tf32f(p11));
        }
        rs0 += __shfl_xor_sync(0xffffffffu, rs0, 1);
        rs0 += __shfl_xor_sync(0xffffffffu, rs0, 2);
        rs1 += __shfl_xor_sync(0xffffffffu, rs1, 1);
        rs1 += __shfl_xor_sync(0xffffffffu, rs1, 2);
        l0 = l0 * a0 + rs0;
        l1 = l1 * a1 + rs1;

#pragma unroll
        for (int dn = 0; dn < 8; dn++) {
            O[dn][0] *= a0; O[dn][1] *= a0;
            O[dn][2] *= a1; O[dn][3] *= a1;
        }
        __syncwarp();

        // ---- O += P @ V, P-frag prefetch pipeline ----
        uint32_t Af[4];
        ldsm4(Af, &Ps[wr + a_row][a_kof]);
#pragma unroll
        for (int j = 0; j < 4; j++) {
            uint32_t Afn[4];
            if (j < 3) ldsm4(Afn, &Ps[wr + a_row][(j + 1) * 8 + a_kof]);
#pragma unroll
            for (int dnp = 0; dnp < 4; dnp++) {
                uint32_t bt[4];
                ldsm4(bt, &Vs[dnp * 16 + b_row][j * 8 + b_kof]);
                mma_tf32(O[dnp * 2 + 0], Af, &bt[0]);
                mma_tf32(O[dnp * 2 + 1], Af, &bt[2]);
            }
            if (j < 3) {
#pragma unroll
                for (int z = 0; z < 4; z++) Af[z] = Afn[z];
            }
        }
    }

    const float inv0 = 1.0f / l0;
    const float inv1 = 1.0f / l1;
    const int b  = bn >> 4;
    const int hn = bn & 15;
    float* orow0 = g_o + (long)(b * SS + r0g) * HH + hn * DD;
    float* orow1 = orow0 + 8 * HH;
#pragma unroll
    for (int dn = 0; dn < 8; dn++) {
        *(float2*)(orow0 + dn * 8 + 2 * c) =
            make_float2(tf32f(O[dn][0] * inv0), tf32f(O[dn][1] * inv0));
        *(float2*)(orow1 + dn * 8 + 2 * c) =
            make_float2(tf32f(O[dn][2] * inv1), tf32f(O[dn][3] * inv1));
    }
}

// ---------------------------------------------------------------------------
extern "C" void kernel_launch(void* const* d_in, const int* in_sizes, int n_in,
                              void* d_out, int out_size)
{
    const float* hs    = (const float*)d_in[0];  // [B,S,H]
    const float* w_in  = (const float*)d_in[1];  // [3H,H]
    const float* b_in  = (const float*)d_in[2];  // [3H]
    const float* w_out = (const float*)d_in[3];  // [H,H]
    const float* b_out = (const float*)d_in[4];  // [H]
    float* out = (float*)d_out;                  // [B,S,H]

    (void)in_sizes; (void)n_in; (void)out_size;

    round_all<<<(NX4 + NWI4 + NWO4) / 256, 256>>>(
        (const float4*)hs, (const float4*)w_in, (const float4*)w_out);

    gemm_mma<0><<<dim3(K3H / NT, MM / MT), 256>>>(b_in, nullptr);
    flash_attn_mma<<<dim3(SS / 128, BB * NH), 256>>>();
    gemm_mma<1><<<dim3(HH / NT, MM / MT), 256>>>(b_out, out);
}